// round 3
// baseline (speedup 1.0000x reference)
#include <cuda_runtime.h>
#include <cstdint>

// Problem constants: T=256, B=32 -> NT=8192 tokens, D_EMBED=128,
// MULTI_INFER_NUM=8 -> NE=9 expert slots (last = overflow).
#define NT 8192
#define D 128
#define NE 9
#define TK 16
#define MAXTILES ((NT + TK - 1) / TK)   // 512

// Scratch (no cudaMalloc allowed): per-expert token lists + counters.
__device__ int g_cnt[NE];
__device__ int g_is_i32;          // 1 if positions buffer is int32, 0 if int64
__device__ int g_list[NE][NT];

// Packed-f32x2 helpers (sm_10x): 2 FMAs per instruction on the fma pipe.
#define FMA_F32X2(d_, a_, b_, c_) \
    asm("fma.rn.f32x2 %0, %1, %2, %3;" : "=l"(d_) : "l"(a_), "l"(b_), "l"(c_))
#define PACK_F32X2(o_, lo_, hi_) \
    asm("mov.b64 %0, {%1, %2};" : "=l"(o_) : "f"(lo_), "f"(hi_))
#define UNPACK_F32X2(lo_, hi_, v_) \
    asm("mov.b64 {%0, %1}, %2;" : "=f"(lo_), "=f"(hi_) : "l"(v_))

// --- Kernel 1: reset counters + dtype flag (graph replayed -> re-zero). ---
__global__ void ltf_zero_kernel() {
    if (threadIdx.x < NE) g_cnt[threadIdx.x] = 0;
    if (threadIdx.x == 31) g_is_i32 = 0;
}

// --- Kernel 1b: dtype probe. Reads odd int32 slots [1,3,..,NT-1] — in-bounds
// for BOTH interpretations (int32 buffer has NT slots; int64 has 2*NT).
// int64 layout: odd slots are high words of values in [0,12) -> all zero.
// int32 layout: odd slots are random values in [0,12) -> some nonzero.
// Deterministic function of input bytes. ---
__global__ void ltf_probe_kernel(const int* __restrict__ pos32) {
    int i = blockIdx.x * blockDim.x + threadIdx.x;   // 0..NT/2-1
    if (i < NT / 2 && pos32[2 * i + 1] != 0) g_is_i32 = 1;
}

// --- Kernel 2: bin tokens by clamped expert id. Atomic order is
// nondeterministic but each token's OUTPUT is computed identically wherever
// it lands in the list, so d_out is deterministic. ---
__global__ void ltf_scatter_kernel(const int* __restrict__ pos32) {
    int t = blockIdx.x * blockDim.x + threadIdx.x;
    if (t >= NT) return;
    // int64 mode: low word at slot 2t (values are tiny, high word irrelevant).
    int p = g_is_i32 ? pos32[t] : pos32[2 * t];
    int r = (p < (NE - 1)) ? p : (NE - 1);
    int slot = atomicAdd(&g_cnt[r], 1);
    g_list[r][slot] = t;
}

// --- Kernel 3: grouped batched matvec, f32x2-packed over the d axis.
// blockIdx.x = expert r, blockIdx.y = token tile. 128 threads, thread == e.
// acc2[tk] holds {sum over even d, sum over odd d}; horizontal add at end.
__global__ __launch_bounds__(128) void ltf_compute_kernel(
    const float* __restrict__ x,     // [NT, D]
    const float* __restrict__ W,     // [NE, D, D]  (d-major, e contiguous)
    const float* __restrict__ b,     // [NE, D]
    float* __restrict__ out)         // [NT, D]
{
    const int r    = blockIdx.x;
    const int cnt  = g_cnt[r];
    const int base = blockIdx.y * TK;
    if (base >= cnt) return;                 // empty tile -> fast exit
    const int n = min(TK, cnt - base);

    __shared__ __align__(16) float xs[TK][D];
    __shared__ int toks[TK];

    const int tid = threadIdx.x;
    if (tid < TK) {
        // Duplicate a valid token for tail slots so addresses stay in-bounds;
        // tail accumulators are computed but never stored.
        toks[tid] = g_list[r][base + ((tid < n) ? tid : 0)];
    }
    __syncthreads();

    // Stage x tile: 32 threads per token, float4 per thread, coalesced.
    #pragma unroll
    for (int idx = tid; idx < TK * 32; idx += 128) {
        const int tk   = idx >> 5;
        const int lane = idx & 31;
        float4 v = *(const float4*)&x[(long)toks[tk] * D + lane * 4];
        *(float4*)&xs[tk][lane * 4] = v;
    }
    __syncthreads();

    const int e = tid;
    const float* Wb = W + (long)r * D * D + e;   // column e of W[r], stride D

    unsigned long long acc2[TK];
    #pragma unroll
    for (int tk = 0; tk < TK; tk++) acc2[tk] = 0ULL;

    // Per 4-d step: 4 coalesced LDGs of W (L1-resident; W[r]=64KB reused TK x
    // per CTA and across co-resident CTAs), 2 packs, 16 LDS.128 broadcasts,
    // 32 FFMA2 (= 64 FMAs). fma-pipe-bound at ~1 cyc per FMA warp-instr.
    #pragma unroll 4
    for (int d = 0; d < D; d += 4) {
        const float w0 = Wb[(d + 0) * D];
        const float w1 = Wb[(d + 1) * D];
        const float w2 = Wb[(d + 2) * D];
        const float w3 = Wb[(d + 3) * D];
        unsigned long long w01, w23;
        PACK_F32X2(w01, w0, w1);
        PACK_F32X2(w23, w2, w3);
        #pragma unroll
        for (int tk = 0; tk < TK; tk++) {
            const ulonglong2 xx = *(const ulonglong2*)&xs[tk][d];  // {d0,d1},{d2,d3}
            unsigned long long a = acc2[tk];
            FMA_F32X2(a, w01, xx.x, a);
            FMA_F32X2(a, w23, xx.y, a);
            acc2[tk] = a;
        }
    }

    const float bv = b[r * D + e];
    #pragma unroll
    for (int tk = 0; tk < TK; tk++) {
        if (tk < n) {
            float lo, hi;
            UNPACK_F32X2(lo, hi, acc2[tk]);
            out[(long)toks[tk] * D + e] = lo + hi + bv;
        }
    }
}

extern "C" void kernel_launch(void* const* d_in, const int* in_sizes, int n_in,
                              void* d_out, int out_size) {
    // metadata order: positions(int[T,B]), outputs(f32[T,B,D]),
    //                 W(f32[NE,D,D]), b(f32[NE,D]); output f32[T,B,D].
    const int*   pos = (const int*)d_in[0];   // dtype resolved on-device
    const float* x   = (const float*)d_in[1];
    const float* W   = (const float*)d_in[2];
    const float* b   = (const float*)d_in[3];
    float*       out = (float*)d_out;

    ltf_zero_kernel<<<1, 32>>>();
    ltf_probe_kernel<<<NT / 2 / 256, 256>>>(pos);
    ltf_scatter_kernel<<<NT / 256, 256>>>(pos);
    dim3 grid(NE, MAXTILES);
    ltf_compute_kernel<<<grid, 128>>>(x, W, b, out);
}

// round 16
// speedup vs baseline: 1.1860x; 1.1860x over previous
#include <cuda_runtime.h>
#include <cstdint>

// Problem constants: T=256, B=32 -> NT=8192 tokens, D_EMBED=128,
// MULTI_INFER_NUM=8 -> NE=9 expert slots (last = overflow).
// positions dtype: int32 on device (JAX x64 disabled). Evidence: Round-2
// kernel reading it as int64 (64KB) crashed OOB; int32 path passes.
#define NT 8192
#define D 128
#define NE 9
#define TK 8
#define NTILES (NT / TK)   // 1024

// Scratch (no cudaMalloc allowed): per-expert token lists + counters.
__device__ int g_cnt[NE];
__device__ int g_list[NE][NT];

// Packed-f32x2 helpers (sm_10x): 2 FMAs per instruction on the fma pipe.
#define FMA_F32X2(d_, a_, b_, c_) \
    asm("fma.rn.f32x2 %0, %1, %2, %3;" : "=l"(d_) : "l"(a_), "l"(b_), "l"(c_))
#define PACK_F32X2(o_, lo_, hi_) \
    asm("mov.b64 %0, {%1, %2};" : "=l"(o_) : "f"(lo_), "f"(hi_))
#define UNPACK_F32X2(lo_, hi_, v_) \
    asm("mov.b64 {%0, %1}, %2;" : "=f"(lo_), "=f"(hi_) : "l"(v_))

// --- Kernel 1: reset counters (graph replayed -> re-zero every launch). ---
__global__ void ltf_zero_kernel() {
    if (threadIdx.x < NE) g_cnt[threadIdx.x] = 0;
}

// --- Kernel 2: bin tokens by clamped expert id. Atomic order is
// nondeterministic but each token's OUTPUT is computed identically wherever
// it lands in the list, so d_out is deterministic. ---
__global__ void ltf_scatter_kernel(const int* __restrict__ pos) {
    int t = blockIdx.x * blockDim.x + threadIdx.x;
    if (t >= NT) return;
    int p = pos[t];
    int r = (p < (NE - 1)) ? p : (NE - 1);
    int slot = atomicAdd(&g_cnt[r], 1);
    g_list[r][slot] = t;
}

// --- Kernel 3: grouped batched matvec, f32x2-packed over d, 2-way d-split.
// blockIdx.x = expert r, blockIdx.y = token tile (TK=8 tokens).
// 256 threads = 2 groups x 128; group g accumulates d in [64g, 64g+64) for
// output dim e = tid&127. Group 1 stages its partial in smem; group 0 adds
// partial + bias and stores. Doubles warps/CTA and live CTAs vs Round 3
// (occ 22.6% -> ~60%) at the same FFMA2 count.
__global__ __launch_bounds__(256) void ltf_compute_kernel(
    const float* __restrict__ x,     // [NT, D]
    const float* __restrict__ W,     // [NE, D, D]  (d-major, e contiguous)
    const float* __restrict__ b,     // [NE, D]
    float* __restrict__ out)         // [NT, D]
{
    const int r    = blockIdx.x;
    const int cnt  = g_cnt[r];
    const int base = blockIdx.y * TK;
    if (base >= cnt) return;                 // empty tile -> fast exit (uniform)
    const int n = min(TK, cnt - base);

    __shared__ __align__(16) float xs[TK][D];
    __shared__ float red[TK][D];             // group-1 partial sums
    __shared__ int toks[TK];

    const int tid = threadIdx.x;
    if (tid < TK) {
        // Duplicate a valid token for tail slots so addresses stay in-bounds;
        // tail results are computed but never stored.
        toks[tid] = g_list[r][base + ((tid < n) ? tid : 0)];
    }
    __syncthreads();

    // Stage x tile: 256 threads cover 8 tokens x 32 lanes, float4, coalesced.
    {
        const int tk   = tid >> 5;
        const int lane = tid & 31;
        float4 v = *(const float4*)&x[(long)toks[tk] * D + lane * 4];
        *(float4*)&xs[tk][lane * 4] = v;
    }
    __syncthreads();

    const int g  = tid >> 7;                 // d-group: 0 or 1
    const int e  = tid & 127;                // output dim
    const int d0 = g * 64;
    const float* Wb = W + (long)r * D * D + (long)d0 * D + e;  // col e, rows d0..

    unsigned long long acc2[TK];
    #pragma unroll
    for (int tk = 0; tk < TK; tk++) acc2[tk] = 0ULL;

    // Per 4-d step: 4 coalesced LDGs of W (L1-resident; W[r]=64KB reused TK x
    // per CTA and across co-resident CTAs), 2 packs, 8 LDS.128 broadcasts,
    // 16 FFMA2 (= 32 FMAs).
    #pragma unroll 4
    for (int d = 0; d < 64; d += 4) {
        const float w0 = Wb[(d + 0) * D];
        const float w1 = Wb[(d + 1) * D];
        const float w2 = Wb[(d + 2) * D];
        const float w3 = Wb[(d + 3) * D];
        unsigned long long w01, w23;
        PACK_F32X2(w01, w0, w1);
        PACK_F32X2(w23, w2, w3);
        #pragma unroll
        for (int tk = 0; tk < TK; tk++) {
            const ulonglong2 xx = *(const ulonglong2*)&xs[tk][d0 + d];
            unsigned long long a = acc2[tk];
            FMA_F32X2(a, w01, xx.x, a);
            FMA_F32X2(a, w23, xx.y, a);
            acc2[tk] = a;
        }
    }

    if (g == 1) {
        #pragma unroll
        for (int tk = 0; tk < TK; tk++) {
            float lo, hi;
            UNPACK_F32X2(lo, hi, acc2[tk]);
            red[tk][e] = lo + hi;            // conflict-free STS
        }
    }
    __syncthreads();

    if (g == 0) {
        const float bv = b[r * D + e];
        #pragma unroll
        for (int tk = 0; tk < TK; tk++) {
            if (tk < n) {
                float lo, hi;
                UNPACK_F32X2(lo, hi, acc2[tk]);
                out[(long)toks[tk] * D + e] = (lo + hi) + red[tk][e] + bv;
            }
        }
    }
}

extern "C" void kernel_launch(void* const* d_in, const int* in_sizes, int n_in,
                              void* d_out, int out_size) {
    // metadata order: positions(int32[T,B]), outputs(f32[T,B,D]),
    //                 W(f32[NE,D,D]), b(f32[NE,D]); output f32[T,B,D].
    const int*   pos = (const int*)d_in[0];
    const float* x   = (const float*)d_in[1];
    const float* W   = (const float*)d_in[2];
    const float* b   = (const float*)d_in[3];
    float*       out = (float*)d_out;

    ltf_zero_kernel<<<1, 32>>>();
    ltf_scatter_kernel<<<NT / 256, 256>>>(pos);
    dim3 grid(NE, NTILES);
    ltf_compute_kernel<<<grid, 256>>>(x, W, b, out);
}